// round 4
// baseline (speedup 1.0000x reference)
#include <cuda_runtime.h>
#include <cstdint>

// ---------------------------------------------------------------------------
// Fused causal flash attention (online softmax), TF32 mma.sync tensor cores.
// Shapes fixed by problem: sq=skv=2048, b=2, h=16, d=128, fp32 in/out, sbhd.
//   q/k/v offset(s, bi, hi, dd) = s*4096 + bi*2048 + hi*128 + dd
//   out   offset(s, bi, hi*128+dd) = same linear address.
// Tiling: block = (BM=128 rows) x (full d=128), 8 warps x 16 rows each.
//         KV tiles of BN=64, looped up to the causal diagonal.
// ---------------------------------------------------------------------------

#define D 128
#define BM 128
#define BN 64
#define NWARPS 8
#define NTHREADS 256

// smem strides (floats), chosen for conflict-free fragment LDS:
//  Q/K: stride%32 == 4  -> bank = (4*row + col)%32 == lane  (A and K-B frags)
//  V:   stride%32 == 8  -> bank = (8*k + n)%32 distinct per lane (V-B frags)
//  P:   stride%32 == 4  -> conflict-free A frags for PV
#define QS_STRIDE 132
#define KS_STRIDE 132
#define VS_STRIDE 136
#define PS_STRIDE 68

#define QS_OFF 0
#define KS_OFF (BM * QS_STRIDE)                    // 16896
#define VS_OFF (KS_OFF + BN * KS_STRIDE)           // 25344
#define PS_OFF (VS_OFF + BN * VS_STRIDE)           // 34048
#define SMEM_FLOATS (PS_OFF + NWARPS * 16 * PS_STRIDE)  // 42752
#define SMEM_BYTES (SMEM_FLOATS * 4)               // 171008

#define NEG_BIG (-1e30f)

__device__ __forceinline__ float to_tf32(float x) {
    uint32_t u;
    asm("cvt.rna.tf32.f32 %0, %1;" : "=r"(u) : "f"(x));
    return __uint_as_float(u);
}

__device__ __forceinline__ void mma_tf32(float d[4],
                                         uint32_t a0, uint32_t a1, uint32_t a2, uint32_t a3,
                                         uint32_t b0, uint32_t b1) {
    asm volatile(
        "mma.sync.aligned.m16n8k8.row.col.f32.tf32.tf32.f32 "
        "{%0,%1,%2,%3}, {%4,%5,%6,%7}, {%8,%9}, {%0,%1,%2,%3};"
        : "+f"(d[0]), "+f"(d[1]), "+f"(d[2]), "+f"(d[3])
        : "r"(a0), "r"(a1), "r"(a2), "r"(a3), "r"(b0), "r"(b1));
}

__global__ __launch_bounds__(NTHREADS, 1)
void fa_causal_tf32_kernel(const float* __restrict__ Q,
                           const float* __restrict__ K,
                           const float* __restrict__ V,
                           float* __restrict__ O) {
    extern __shared__ float sm[];
    float* Qs = sm + QS_OFF;
    float* Ks = sm + KS_OFF;
    float* Vs = sm + VS_OFF;
    float* Ps = sm + PS_OFF;

    const int tid  = threadIdx.x;
    const int warp = tid >> 5;
    const int lane = tid & 31;
    const int qid  = lane >> 2;   // groupID (0..7)
    const int t    = lane & 3;    // threadID_in_group (0..3)

    // Reverse m-tile order: heaviest causal blocks scheduled first.
    const int mi   = (int)(gridDim.x - 1) - (int)blockIdx.x;
    const int row0 = mi * BM;
    const int bh   = blockIdx.y;                 // 0..31
    const int bi   = bh >> 4, hi = bh & 15;
    const size_t base = (size_t)bi * 2048 + (size_t)hi * 128;
    const float scale = 0.08838834764831845f;    // 1/sqrt(128)

    // ---- stage Q tile (scaled + tf32-rounded) ----
    for (int idx = tid; idx < BM * (D / 4); idx += NTHREADS) {
        const int r = idx >> 5;
        const int c = (idx & 31) << 2;
        const float4 v = *reinterpret_cast<const float4*>(
            Q + (size_t)(row0 + r) * 4096 + base + c);
        float4 w;
        w.x = to_tf32(v.x * scale);
        w.y = to_tf32(v.y * scale);
        w.z = to_tf32(v.z * scale);
        w.w = to_tf32(v.w * scale);
        *reinterpret_cast<float4*>(Qs + r * QS_STRIDE + c) = w;
    }

    // ---- per-thread accumulator state (2 rows: qid and qid+8 of warp tile) ----
    float o[16][4];
#pragma unroll
    for (int n = 0; n < 16; n++) { o[n][0] = o[n][1] = o[n][2] = o[n][3] = 0.f; }
    float m0 = NEG_BIG, m1 = NEG_BIG, l0 = 0.f, l1 = 0.f;

    const int wr0   = warp * 16;
    const int grow0 = row0 + wr0;                // warp's first global row
    const int i0    = grow0 + qid;
    const int i1    = i0 + 8;
    float* Pw = Ps + warp * 16 * PS_STRIDE;

    const int ntiles = (row0 + BM) / BN;         // tiles up to causal diagonal

    for (int tile = 0; tile < ntiles; tile++) {
        const int kv0 = tile * BN;

        __syncthreads();  // previous iteration done reading Ks/Vs
        // ---- stage K and V tiles (tf32-rounded) ----
        for (int idx = tid; idx < BN * (D / 4); idx += NTHREADS) {
            const int r = idx >> 5;
            const int c = (idx & 31) << 2;
            const size_t g = (size_t)(kv0 + r) * 4096 + base + c;
            const float4 kv = *reinterpret_cast<const float4*>(K + g);
            const float4 vv = *reinterpret_cast<const float4*>(V + g);
            float4 kw, vw;
            kw.x = to_tf32(kv.x); kw.y = to_tf32(kv.y);
            kw.z = to_tf32(kv.z); kw.w = to_tf32(kv.w);
            vw.x = to_tf32(vv.x); vw.y = to_tf32(vv.y);
            vw.z = to_tf32(vv.z); vw.w = to_tf32(vv.w);
            *reinterpret_cast<float4*>(Ks + r * KS_STRIDE + c) = kw;
            *reinterpret_cast<float4*>(Vs + r * VS_STRIDE + c) = vw;
        }
        __syncthreads();

        // Warp entirely above the diagonal for this tile -> all masked, skip.
        if (kv0 > grow0 + 15) continue;

        // ---- S = Q * K^T  (16x64 per warp, 16 k-steps of 8) ----
        float s[8][4];
#pragma unroll
        for (int n = 0; n < 8; n++) s[n][0] = s[n][1] = s[n][2] = s[n][3] = 0.f;

#pragma unroll
        for (int k = 0; k < 16; k++) {
            const float* qb = Qs + (wr0 + qid) * QS_STRIDE + (k << 3) + t;
            const uint32_t a0 = __float_as_uint(qb[0]);
            const uint32_t a1 = __float_as_uint(qb[8 * QS_STRIDE]);
            const uint32_t a2 = __float_as_uint(qb[4]);
            const uint32_t a3 = __float_as_uint(qb[8 * QS_STRIDE + 4]);
#pragma unroll
            for (int n = 0; n < 8; n++) {
                const float* kb = Ks + ((n << 3) + qid) * KS_STRIDE + (k << 3) + t;
                const uint32_t b0 = __float_as_uint(kb[0]);
                const uint32_t b1 = __float_as_uint(kb[4]);
                mma_tf32(s[n], a0, a1, a2, a3, b0, b1);
            }
        }

        // ---- causal mask (only tiles that can touch the diagonal) ----
        if (kv0 + BN - 1 > i0) {
#pragma unroll
            for (int n = 0; n < 8; n++) {
                const int j = kv0 + (n << 3) + (t << 1);
                if (j     > i0) s[n][0] = NEG_BIG;
                if (j + 1 > i0) s[n][1] = NEG_BIG;
                if (j     > i1) s[n][2] = NEG_BIG;
                if (j + 1 > i1) s[n][3] = NEG_BIG;
            }
        }

        // ---- online softmax update ----
        float mx0 = NEG_BIG, mx1 = NEG_BIG;
#pragma unroll
        for (int n = 0; n < 8; n++) {
            mx0 = fmaxf(mx0, fmaxf(s[n][0], s[n][1]));
            mx1 = fmaxf(mx1, fmaxf(s[n][2], s[n][3]));
        }
        mx0 = fmaxf(mx0, __shfl_xor_sync(0xffffffffu, mx0, 1));
        mx0 = fmaxf(mx0, __shfl_xor_sync(0xffffffffu, mx0, 2));
        mx1 = fmaxf(mx1, __shfl_xor_sync(0xffffffffu, mx1, 1));
        mx1 = fmaxf(mx1, __shfl_xor_sync(0xffffffffu, mx1, 2));

        const float mn0 = fmaxf(m0, mx0);
        const float mn1 = fmaxf(m1, mx1);
        const float al0 = __expf(m0 - mn0);
        const float al1 = __expf(m1 - mn1);

        float sum0 = 0.f, sum1 = 0.f;
#pragma unroll
        for (int n = 0; n < 8; n++) {
            s[n][0] = __expf(s[n][0] - mn0);
            s[n][1] = __expf(s[n][1] - mn0);
            s[n][2] = __expf(s[n][2] - mn1);
            s[n][3] = __expf(s[n][3] - mn1);
            sum0 += s[n][0] + s[n][1];
            sum1 += s[n][2] + s[n][3];
        }
        sum0 += __shfl_xor_sync(0xffffffffu, sum0, 1);
        sum0 += __shfl_xor_sync(0xffffffffu, sum0, 2);
        sum1 += __shfl_xor_sync(0xffffffffu, sum1, 1);
        sum1 += __shfl_xor_sync(0xffffffffu, sum1, 2);

        l0 = l0 * al0 + sum0;
        l1 = l1 * al1 + sum1;
        m0 = mn0;
        m1 = mn1;
#pragma unroll
        for (int n = 0; n < 16; n++) {
            o[n][0] *= al0; o[n][1] *= al0;
            o[n][2] *= al1; o[n][3] *= al1;
        }

        // ---- stage P (tf32-rounded) to warp-private smem for the PV mma ----
#pragma unroll
        for (int n = 0; n < 8; n++) {
            const float2 p01 = make_float2(to_tf32(s[n][0]), to_tf32(s[n][1]));
            const float2 p23 = make_float2(to_tf32(s[n][2]), to_tf32(s[n][3]));
            *reinterpret_cast<float2*>(Pw + qid * PS_STRIDE + (n << 3) + (t << 1)) = p01;
            *reinterpret_cast<float2*>(Pw + (qid + 8) * PS_STRIDE + (n << 3) + (t << 1)) = p23;
        }
        __syncwarp();

        // ---- O += P * V  (16x128 per warp, 8 k-steps of 8) ----
#pragma unroll
        for (int k = 0; k < 8; k++) {
            const float* pb = Pw + qid * PS_STRIDE + (k << 3) + t;
            const uint32_t a0 = __float_as_uint(pb[0]);
            const uint32_t a1 = __float_as_uint(pb[8 * PS_STRIDE]);
            const uint32_t a2 = __float_as_uint(pb[4]);
            const uint32_t a3 = __float_as_uint(pb[8 * PS_STRIDE + 4]);
#pragma unroll
            for (int n = 0; n < 16; n++) {
                const float* vb = Vs + ((k << 3) + t) * VS_STRIDE + (n << 3) + qid;
                const uint32_t b0 = __float_as_uint(vb[0]);
                const uint32_t b1 = __float_as_uint(vb[4 * VS_STRIDE]);
                mma_tf32(o[n], a0, a1, a2, a3, b0, b1);
            }
        }
    }

    // ---- epilogue: normalize and store (float2 pairs are contiguous cols) ----
    const float inv0 = 1.f / l0;
    const float inv1 = 1.f / l1;
    const size_t ob0 = (size_t)i0 * 4096 + base;
    const size_t ob1 = ob0 + (size_t)8 * 4096;
#pragma unroll
    for (int n = 0; n < 16; n++) {
        const int c = (n << 3) + (t << 1);
        *reinterpret_cast<float2*>(O + ob0 + c) =
            make_float2(o[n][0] * inv0, o[n][1] * inv0);
        *reinterpret_cast<float2*>(O + ob1 + c) =
            make_float2(o[n][2] * inv1, o[n][3] * inv1);
    }
}

extern "C" void kernel_launch(void* const* d_in, const int* in_sizes, int n_in,
                              void* d_out, int out_size) {
    const float* q = (const float*)d_in[0];
    const float* k = (const float*)d_in[1];
    const float* v = (const float*)d_in[2];
    float* out = (float*)d_out;

    (void)in_sizes; (void)n_in; (void)out_size;

    cudaFuncSetAttribute(fa_causal_tf32_kernel,
                         cudaFuncAttributeMaxDynamicSharedMemorySize, SMEM_BYTES);

    dim3 grid(2048 / BM, 2 * 16);   // (16 m-tiles, 32 batch*head)
    fa_causal_tf32_kernel<<<grid, NTHREADS, SMEM_BYTES>>>(q, k, v, out);
}

// round 6
// speedup vs baseline: 1.2729x; 1.2729x over previous
#include <cuda_runtime.h>
#include <cstdint>

// ---------------------------------------------------------------------------
// Fused causal flash attention (online softmax), TF32 mma.sync tensor cores.
// R4: cp.async double-buffered K/V (overlap load & compute, HW tf32 truncation),
//     P smem round-trip replaced by register shuffle-transpose, exp2f softmax.
// Shapes fixed: sq=skv=2048, b=2, h=16, d=128, fp32 in/out, sbhd layout.
// ---------------------------------------------------------------------------

#define D 128
#define BM 128
#define BN 64
#define NWARPS 8
#define NTHREADS 256

// smem strides (floats), conflict-free fragment LDS:
//  Q/K: stride%32==4 -> bank=(4*row+col)%32 == lane
//  V:   stride%32==8 -> bank=(8*k+n)%32 distinct per lane
#define QS_STRIDE 132
#define KS_STRIDE 132
#define VS_STRIDE 136

#define QS_OFF 0
#define KS_OFF (BM * QS_STRIDE)                   // 16896
#define KS_SZ  (BN * KS_STRIDE)                   // 8448
#define VS_OFF (KS_OFF + 2 * KS_SZ)               // 33792
#define VS_SZ  (BN * VS_STRIDE)                   // 8704
#define SMEM_FLOATS (VS_OFF + 2 * VS_SZ)          // 51200
#define SMEM_BYTES (SMEM_FLOATS * 4)              // 204800

#define NEG_BIG (-1e30f)

__device__ __forceinline__ float to_tf32(float x) {
    uint32_t u;
    asm("cvt.rna.tf32.f32 %0, %1;" : "=r"(u) : "f"(x));
    return __uint_as_float(u);
}

__device__ __forceinline__ void mma_tf32(float d[4],
                                         uint32_t a0, uint32_t a1, uint32_t a2, uint32_t a3,
                                         uint32_t b0, uint32_t b1) {
    asm volatile(
        "mma.sync.aligned.m16n8k8.row.col.f32.tf32.tf32.f32 "
        "{%0,%1,%2,%3}, {%4,%5,%6,%7}, {%8,%9}, {%0,%1,%2,%3};"
        : "+f"(d[0]), "+f"(d[1]), "+f"(d[2]), "+f"(d[3])
        : "r"(a0), "r"(a1), "r"(a2), "r"(a3), "r"(b0), "r"(b1));
}

__device__ __forceinline__ void cp_async16(uint32_t saddr, const void* gptr) {
    asm volatile("cp.async.cg.shared.global [%0], [%1], 16;\n"
                 :: "r"(saddr), "l"(gptr));
}
__device__ __forceinline__ void cp_commit() {
    asm volatile("cp.async.commit_group;\n" ::: "memory");
}
template <int N>
__device__ __forceinline__ void cp_wait() {
    asm volatile("cp.async.wait_group %0;\n" :: "n"(N) : "memory");
}

__global__ __launch_bounds__(NTHREADS, 1)
void fa_causal_tf32_kernel(const float* __restrict__ Q,
                           const float* __restrict__ K,
                           const float* __restrict__ V,
                           float* __restrict__ O) {
    extern __shared__ float sm[];
    float* Qs = sm + QS_OFF;

    const int tid  = threadIdx.x;
    const int warp = tid >> 5;
    const int lane = tid & 31;
    const int qid  = lane >> 2;   // groupID (0..7)
    const int t    = lane & 3;    // threadID_in_group (0..3)

    // Reverse m-tile order: heaviest causal blocks first.
    const int mi   = (int)(gridDim.x - 1) - (int)blockIdx.x;
    const int row0 = mi * BM;
    const int bh   = blockIdx.y;
    const int bi   = bh >> 4, hi = bh & 15;
    const size_t base = (size_t)bi * 2048 + (size_t)hi * 128;
    // 1/sqrt(128) * log2(e): softmax in base-2
    const float scale = 0.08838834764831845f * 1.4426950408889634f;

    const uint32_t smem_u32 = (uint32_t)__cvta_generic_to_shared(sm);
    const int ntiles = (row0 + BM) / BN;

    // ---- prologue: issue cp.async for tile 0 (K/V raw fp32 -> smem) ----
    {
        const float* Kg = K + base;
        const float* Vg = V + base;
#pragma unroll
        for (int it = 0; it < 8; it++) {
            const int idx = tid + it * NTHREADS;   // 0..2047
            const int r = idx >> 5;
            const int c = (idx & 31) << 2;
            cp_async16(smem_u32 + (uint32_t)(KS_OFF + r * KS_STRIDE + c) * 4,
                       Kg + (size_t)r * 4096 + c);
            cp_async16(smem_u32 + (uint32_t)(VS_OFF + r * VS_STRIDE + c) * 4,
                       Vg + (size_t)r * 4096 + c);
        }
        cp_commit();
    }

    // ---- stage Q tile (scaled + tf32 RNA) — overlaps tile-0 cp.async ----
    for (int idx = tid; idx < BM * (D / 4); idx += NTHREADS) {
        const int r = idx >> 5;
        const int c = (idx & 31) << 2;
        const float4 v = *reinterpret_cast<const float4*>(
            Q + (size_t)(row0 + r) * 4096 + base + c);
        float4 w;
        w.x = to_tf32(v.x * scale);
        w.y = to_tf32(v.y * scale);
        w.z = to_tf32(v.z * scale);
        w.w = to_tf32(v.w * scale);
        *reinterpret_cast<float4*>(Qs + r * QS_STRIDE + c) = w;
    }

    // ---- per-thread accumulator state (rows qid, qid+8 of warp tile) ----
    float o[16][4];
#pragma unroll
    for (int n = 0; n < 16; n++) { o[n][0] = o[n][1] = o[n][2] = o[n][3] = 0.f; }
    float m0 = NEG_BIG, m1 = NEG_BIG, l0 = 0.f, l1 = 0.f;

    const int wr0   = warp * 16;
    const int grow0 = row0 + wr0;
    const int i0    = grow0 + qid;
    const int i1    = i0 + 8;

    for (int tile = 0; tile < ntiles; tile++) {
        const int kv0 = tile * BN;
        float* Ks = sm + KS_OFF + (tile & 1) * KS_SZ;
        float* Vs = sm + VS_OFF + (tile & 1) * VS_SZ;

        // ---- issue next tile's cp.async into the other buffer ----
        if (tile + 1 < ntiles) {
            const int nb = (tile + 1) & 1;
            const float* Kg = K + (size_t)(kv0 + BN) * 4096 + base;
            const float* Vg = V + (size_t)(kv0 + BN) * 4096 + base;
            const uint32_t kbase = smem_u32 + (uint32_t)(KS_OFF + nb * KS_SZ) * 4;
            const uint32_t vbase = smem_u32 + (uint32_t)(VS_OFF + nb * VS_SZ) * 4;
#pragma unroll
            for (int it = 0; it < 8; it++) {
                const int idx = tid + it * NTHREADS;
                const int r = idx >> 5;
                const int c = (idx & 31) << 2;
                cp_async16(kbase + (uint32_t)(r * KS_STRIDE + c) * 4,
                           Kg + (size_t)r * 4096 + c);
                cp_async16(vbase + (uint32_t)(r * VS_STRIDE + c) * 4,
                           Vg + (size_t)r * 4096 + c);
            }
            cp_commit();
            cp_wait<1>();          // current tile's group complete
        } else {
            cp_wait<0>();
        }
        __syncthreads();           // all threads' copies visible (+ Q on tile 0)

        // Warp entirely above the diagonal -> all masked, skip compute.
        if (kv0 <= grow0 + 15) {
            // ---- S = Q * K^T (16x64 per warp, 16 k-steps of 8) ----
            float s[8][4];
#pragma unroll
            for (int n = 0; n < 8; n++) s[n][0] = s[n][1] = s[n][2] = s[n][3] = 0.f;

#pragma unroll
            for (int k = 0; k < 16; k++) {
                const float* qb = Qs + (wr0 + qid) * QS_STRIDE + (k << 3) + t;
                const uint32_t a0 = __float_as_uint(qb[0]);
                const uint32_t a1 = __float_as_uint(qb[8 * QS_STRIDE]);
                const uint32_t a2 = __float_as_uint(qb[4]);
                const uint32_t a3 = __float_as_uint(qb[8 * QS_STRIDE + 4]);
#pragma unroll
                for (int n = 0; n < 8; n++) {
                    const float* kb = Ks + ((n << 3) + qid) * KS_STRIDE + (k << 3) + t;
                    mma_tf32(s[n], a0, a1, a2, a3,
                             __float_as_uint(kb[0]), __float_as_uint(kb[4]));
                }
            }

            // ---- causal mask ----
            if (kv0 + BN - 1 > i0) {
#pragma unroll
                for (int n = 0; n < 8; n++) {
                    const int j = kv0 + (n << 3) + (t << 1);
                    if (j     > i0) s[n][0] = NEG_BIG;
                    if (j + 1 > i0) s[n][1] = NEG_BIG;
                    if (j     > i1) s[n][2] = NEG_BIG;
                    if (j + 1 > i1) s[n][3] = NEG_BIG;
                }
            }

            // ---- online softmax (base-2) ----
            float mx0 = NEG_BIG, mx1 = NEG_BIG;
#pragma unroll
            for (int n = 0; n < 8; n++) {
                mx0 = fmaxf(mx0, fmaxf(s[n][0], s[n][1]));
                mx1 = fmaxf(mx1, fmaxf(s[n][2], s[n][3]));
            }
            mx0 = fmaxf(mx0, __shfl_xor_sync(0xffffffffu, mx0, 1));
            mx0 = fmaxf(mx0, __shfl_xor_sync(0xffffffffu, mx0, 2));
            mx1 = fmaxf(mx1, __shfl_xor_sync(0xffffffffu, mx1, 1));
            mx1 = fmaxf(mx1, __shfl_xor_sync(0xffffffffu, mx1, 2));

            const float mn0 = fmaxf(m0, mx0);
            const float mn1 = fmaxf(m1, mx1);
            const float al0 = exp2f(m0 - mn0);
            const float al1 = exp2f(m1 - mn1);

            float sum0 = 0.f, sum1 = 0.f;
#pragma unroll
            for (int n = 0; n < 8; n++) {
                s[n][0] = exp2f(s[n][0] - mn0);
                s[n][1] = exp2f(s[n][1] - mn0);
                s[n][2] = exp2f(s[n][2] - mn1);
                s[n][3] = exp2f(s[n][3] - mn1);
                sum0 += s[n][0] + s[n][1];
                sum1 += s[n][2] + s[n][3];
            }
            sum0 += __shfl_xor_sync(0xffffffffu, sum0, 1);
            sum0 += __shfl_xor_sync(0xffffffffu, sum0, 2);
            sum1 += __shfl_xor_sync(0xffffffffu, sum1, 1);
            sum1 += __shfl_xor_sync(0xffffffffu, sum1, 2);

            l0 = l0 * al0 + sum0;
            l1 = l1 * al1 + sum1;
            m0 = mn0;
            m1 = mn1;
#pragma unroll
            for (int n = 0; n < 16; n++) {
                o[n][0] *= al0; o[n][1] *= al0;
                o[n][2] *= al1; o[n][3] *= al1;
            }

            // ---- O += P * V, P via register shuffle-transpose (C->A frag) ----
            // A-frag for k-group g: a0=P[qid][8g+t], a1=P[qid+8][8g+t],
            //                       a2=P[qid][8g+t+4], a3=P[qid+8][8g+t+4]
            // source lanes: srcA = qid*4 + (t>>1), srcB = srcA + 2; reg by t&1.
            const int srcA = (lane & 28) | (t >> 1);
            const int srcB = srcA + 2;
            const bool odd = (t & 1);
#pragma unroll
            for (int g = 0; g < 8; g++) {
                const float p0 = __shfl_sync(0xffffffffu, s[g][0], srcA);
                const float p1 = __shfl_sync(0xffffffffu, s[g][1], srcA);
                const float p2 = __shfl_sync(0xffffffffu, s[g][2], srcA);
                const float p3 = __shfl_sync(0xffffffffu, s[g][3], srcA);
                const float q0 = __shfl_sync(0xffffffffu, s[g][0], srcB);
                const float q1 = __shfl_sync(0xffffffffu, s[g][1], srcB);
                const float q2 = __shfl_sync(0xffffffffu, s[g][2], srcB);
                const float q3 = __shfl_sync(0xffffffffu, s[g][3], srcB);
                const uint32_t a0 = __float_as_uint(to_tf32(odd ? p1 : p0));
                const uint32_t a1 = __float_as_uint(to_tf32(odd ? p3 : p2));
                const uint32_t a2 = __float_as_uint(to_tf32(odd ? q1 : q0));
                const uint32_t a3 = __float_as_uint(to_tf32(odd ? q3 : q2));
#pragma unroll
                for (int n = 0; n < 16; n++) {
                    const float* vb = Vs + ((g << 3) + t) * VS_STRIDE + (n << 3) + qid;
                    mma_tf32(o[n], a0, a1, a2, a3,
                             __float_as_uint(vb[0]),
                             __float_as_uint(vb[4 * VS_STRIDE]));
                }
            }
        }

        __syncthreads();   // all warps done with buf[tile&1] before it is refilled
    }

    // ---- epilogue: normalize and store ----
    const float inv0 = 1.f / l0;
    const float inv1 = 1.f / l1;
    const size_t ob0 = (size_t)i0 * 4096 + base;
    const size_t ob1 = ob0 + (size_t)8 * 4096;
#pragma unroll
    for (int n = 0; n < 16; n++) {
        const int c = (n << 3) + (t << 1);
        *reinterpret_cast<float2*>(O + ob0 + c) =
            make_float2(o[n][0] * inv0, o[n][1] * inv0);
        *reinterpret_cast<float2*>(O + ob1 + c) =
            make_float2(o[n][2] * inv1, o[n][3] * inv1);
    }
}

extern "C" void kernel_launch(void* const* d_in, const int* in_sizes, int n_in,
                              void* d_out, int out_size) {
    const float* q = (const float*)d_in[0];
    const float* k = (const float*)d_in[1];
    const float* v = (const float*)d_in[2];
    float* out = (float*)d_out;

    (void)in_sizes; (void)n_in; (void)out_size;

    cudaFuncSetAttribute(fa_causal_tf32_kernel,
                         cudaFuncAttributeMaxDynamicSharedMemorySize, SMEM_BYTES);

    dim3 grid(2048 / BM, 2 * 16);
    fa_causal_tf32_kernel<<<grid, NTHREADS, SMEM_BYTES>>>(q, k, v, out);
}